// round 15
// baseline (speedup 1.0000x reference)
#include <cuda_runtime.h>
#include <math.h>

// input_feats: [B=8, L=4096, C=2048] fp32   (H = W = 64)
// points_yx:   [B=8, M=4, P=512, 2] fp32
// output:      [B=8, M=4, O=64, C=2048] fp32
//
// out[b,m,o,c] = sum_{j=0..31} w_j * feat[b, idx_j, c]
// (32 pairs = 8 points x 4 bilinear corners, weights pre-divided by 8)
//
// FINAL: at the LTS (L2 data-path) ceiling. ~528 MB through L2 (512 MB
// structurally-irreducible gather reads = 65536 contributions x 8 KB,
// + 16 MB writes) at ~11.8-12.3 TB/s ~= 6200-6300 B/cyc @NAT — the
// HW-measured path-independent LTS cap. DRAM bytes at the unique-
// footprint floor (~245 MB). This exact binary: 43.0/46.0/45.5/44.6/
// 45.2 us over five runs (NAT DVFS jitter, sigma ~1 us). Config space
// (occ 44-88%, MLP 2-8, sorted/unsorted, LDG/LDGSTS/ldcg, SMEM/shuffle
// staging, full/half-row CTAs) is flat within that band. All traffic-
// reducing restructures rejected with quantified mechanisms (scatter
// 2x RMW; cluster dedup 3% < sync cost; mask dedup trades 21% L2 for
// >= equal SMEM-RMW; L1 reuse ~0.8%).
//
// Config: grid 4096 = 2 CTAs per output row (channel halves; keeps the
// concurrent-CTA L2 window at ~1.2 batches so DRAM stays at the floor),
// occ 4 (64-reg budget), UF=8 front-batched float4 loads, SMEM-staged
// (idx, weight) pairs, streaming stores for the never-re-read output.

#define H 64
#define W 64
#define C 2048
#define CV4 (C / 4)
#define M_MASKS 4
#define P_PTS 512
#define O_POOL 64
#define KCHUNK 8
#define NPAIR 32
#define UF 8

__global__ __launch_bounds__(256, 4)
void point_sample_pool_kernel(const float* __restrict__ feats,
                              const float* __restrict__ pts,
                              float* __restrict__ out)
{
    // blockIdx.x in [0, 4096): bmo*2 + half (b-major ordering preserved)
    const int half = blockIdx.x & 1;
    const int bmo  = blockIdx.x >> 1;
    const int o    = bmo & (O_POOL - 1);
    const int bm   = bmo >> 6;               // b*4 + m
    const int b    = bm >> 2;

    __shared__ int   s_idx[NPAIR];
    __shared__ float s_w[NPAIR];

    const int tid = threadIdx.x;

    if (tid < NPAIR) {
        const int p_local = tid >> 2;
        const int corner  = tid & 3;
        const int p = o * KCHUNK + p_local;
        const float* pp = pts + ((size_t)bm * P_PTS + p) * 2;
        const float iy = pp[0] * (float)(H - 1);
        const float ix = pp[1] * (float)(W - 1);
        const float y0f = floorf(iy);
        const float x0f = floorf(ix);
        const float wy = iy - y0f;
        const float wx = ix - x0f;
        int y0 = (int)y0f; y0 = max(0, min(y0, H - 1));
        int x0 = (int)x0f; x0 = max(0, min(x0, W - 1));
        const int y1 = min(y0 + 1, H - 1);
        const int x1 = min(x0 + 1, W - 1);

        const int   yi  = (corner & 2) ? y1 : y0;
        const int   xi  = (corner & 1) ? x1 : x0;
        const float wyc = (corner & 2) ? wy : (1.0f - wy);
        const float wxc = (corner & 1) ? wx : (1.0f - wx);

        s_idx[tid] = yi * W + xi;
        s_w[tid]   = wyc * wxc * (1.0f / (float)KCHUNK);
    }
    __syncthreads();

    const float4* base = (const float4*)(feats + (size_t)b * (H * W) * C);

    // This CTA owns float4 slots [half*256, half*256+256)
    const int c4 = half * 256 + tid;

    float4 acc0 = make_float4(0.f, 0.f, 0.f, 0.f);
    float4 acc1 = make_float4(0.f, 0.f, 0.f, 0.f);

    #pragma unroll
    for (int j0 = 0; j0 < NPAIR; j0 += UF) {
        float4 v[UF];
        // Front-batch UF independent loads (MLP_p1 = UF)
        #pragma unroll
        for (int u = 0; u < UF; u++) {
            v[u] = __ldg(base + (size_t)s_idx[j0 + u] * CV4 + c4);
        }
        // Then consume
        #pragma unroll
        for (int u = 0; u < UF; u++) {
            const float w = s_w[j0 + u];
            float4& a = (u & 1) ? acc1 : acc0;
            a.x = fmaf(w, v[u].x, a.x);
            a.y = fmaf(w, v[u].y, a.y);
            a.z = fmaf(w, v[u].z, a.z);
            a.w = fmaf(w, v[u].w, a.w);
        }
    }

    acc0.x += acc1.x; acc0.y += acc1.y; acc0.z += acc1.z; acc0.w += acc1.w;

    // Streaming store: output is never re-read.
    float4* op = (float4*)(out + (size_t)bmo * C) + c4;
    __stcs(op, acc0);
}

extern "C" void kernel_launch(void* const* d_in, const int* in_sizes, int n_in,
                              void* d_out, int out_size)
{
    const float* feats = (const float*)d_in[0];
    const float* pts   = (const float*)d_in[1];
    float* out = (float*)d_out;

    const int grid = 8 * M_MASKS * O_POOL * 2;   // 4096 CTAs
    point_sample_pool_kernel<<<grid, 256>>>(feats, pts, out);
}

// round 16
// speedup vs baseline: 1.0335x; 1.0335x over previous
#include <cuda_runtime.h>
#include <math.h>

// input_feats: [B=8, L=4096, C=2048] fp32   (H = W = 64)
// points_yx:   [B=8, M=4, P=512, 2] fp32
// output:      [B=8, M=4, O=64, C=2048] fp32
//
// out[b,m,o,c] = sum_{j=0..31} w_j * feat[b, idx_j, c]
// (32 pairs = 8 points x 4 bilinear corners, weights pre-divided by 8)
//
// Round-16: the winning R3/R10 config with ONE change: gather loads use
// __ldcg (L2-only, skip L1 insertion). Measured L1 reuse is ~0.8% — L1
// allocation is pure pollution/overhead. This is the last untested
// isolated knob; everything else (occ 44-88%, MLP 2-8, ordering, LDGSTS,
// SMEM/shuffle staging, CTA shape) measured flat within the ~1 us NAT
// DVFS noise band around the 44.9 us mean. Kernel is at the LTS cap:
// 528 MB through L2 at ~6200 B/cyc.
//
// Config: grid 4096 = 2 CTAs per output row (channel halves; L2 window
// ~1.2 batches so DRAM stays at the unique-footprint floor ~245 MB),
// occ 4 (64-reg budget), UF=8 front-batched float4 loads, SMEM-staged
// (idx, weight) pairs, streaming stores for the never-re-read output.

#define H 64
#define W 64
#define C 2048
#define CV4 (C / 4)
#define M_MASKS 4
#define P_PTS 512
#define O_POOL 64
#define KCHUNK 8
#define NPAIR 32
#define UF 8

__global__ __launch_bounds__(256, 4)
void point_sample_pool_kernel(const float* __restrict__ feats,
                              const float* __restrict__ pts,
                              float* __restrict__ out)
{
    // blockIdx.x in [0, 4096): bmo*2 + half (b-major ordering preserved)
    const int half = blockIdx.x & 1;
    const int bmo  = blockIdx.x >> 1;
    const int o    = bmo & (O_POOL - 1);
    const int bm   = bmo >> 6;               // b*4 + m
    const int b    = bm >> 2;

    __shared__ int   s_idx[NPAIR];
    __shared__ float s_w[NPAIR];

    const int tid = threadIdx.x;

    if (tid < NPAIR) {
        const int p_local = tid >> 2;
        const int corner  = tid & 3;
        const int p = o * KCHUNK + p_local;
        const float* pp = pts + ((size_t)bm * P_PTS + p) * 2;
        const float iy = pp[0] * (float)(H - 1);
        const float ix = pp[1] * (float)(W - 1);
        const float y0f = floorf(iy);
        const float x0f = floorf(ix);
        const float wy = iy - y0f;
        const float wx = ix - x0f;
        int y0 = (int)y0f; y0 = max(0, min(y0, H - 1));
        int x0 = (int)x0f; x0 = max(0, min(x0, W - 1));
        const int y1 = min(y0 + 1, H - 1);
        const int x1 = min(x0 + 1, W - 1);

        const int   yi  = (corner & 2) ? y1 : y0;
        const int   xi  = (corner & 1) ? x1 : x0;
        const float wyc = (corner & 2) ? wy : (1.0f - wy);
        const float wxc = (corner & 1) ? wx : (1.0f - wx);

        s_idx[tid] = yi * W + xi;
        s_w[tid]   = wyc * wxc * (1.0f / (float)KCHUNK);
    }
    __syncthreads();

    const float4* base = (const float4*)(feats + (size_t)b * (H * W) * C);

    // This CTA owns float4 slots [half*256, half*256+256)
    const int c4 = half * 256 + tid;

    float4 acc0 = make_float4(0.f, 0.f, 0.f, 0.f);
    float4 acc1 = make_float4(0.f, 0.f, 0.f, 0.f);

    #pragma unroll
    for (int j0 = 0; j0 < NPAIR; j0 += UF) {
        float4 v[UF];
        // Front-batch UF independent loads (MLP_p1 = UF), L2-only.
        #pragma unroll
        for (int u = 0; u < UF; u++) {
            v[u] = __ldcg(base + (size_t)s_idx[j0 + u] * CV4 + c4);
        }
        // Then consume
        #pragma unroll
        for (int u = 0; u < UF; u++) {
            const float w = s_w[j0 + u];
            float4& a = (u & 1) ? acc1 : acc0;
            a.x = fmaf(w, v[u].x, a.x);
            a.y = fmaf(w, v[u].y, a.y);
            a.z = fmaf(w, v[u].z, a.z);
            a.w = fmaf(w, v[u].w, a.w);
        }
    }

    acc0.x += acc1.x; acc0.y += acc1.y; acc0.z += acc1.z; acc0.w += acc1.w;

    // Streaming store: output is never re-read.
    float4* op = (float4*)(out + (size_t)bmo * C) + c4;
    __stcs(op, acc0);
}

extern "C" void kernel_launch(void* const* d_in, const int* in_sizes, int n_in,
                              void* d_out, int out_size)
{
    const float* feats = (const float*)d_in[0];
    const float* pts   = (const float*)d_in[1];
    float* out = (float*)d_out;

    const int grid = 8 * M_MASKS * O_POOL * 2;   // 4096 CTAs
    point_sample_pool_kernel<<<grid, 256>>>(feats, pts, out);
}

// round 17
// speedup vs baseline: 1.0401x; 1.0063x over previous
#include <cuda_runtime.h>
#include <math.h>

// input_feats: [B=8, L=4096, C=2048] fp32   (H = W = 64)
// points_yx:   [B=8, M=4, P=512, 2] fp32
// output:      [B=8, M=4, O=64, C=2048] fp32
//
// out[b,m,o,c] = sum_{j=0..31} w_j * feat[b, idx_j, c]
// (32 pairs = 8 points x 4 bilinear corners, weights pre-divided by 8)
//
// FINAL: at the LTS (L2 data-path) ceiling. ~528 MB through L2 (512 MB
// structurally-irreducible gather reads = 65536 contributions x 8 KB,
// + 16 MB writes) at ~12.1 TB/s ~= 6200 B/cyc @NAT — the HW-measured
// path-independent LTS cap. DRAM bytes at the unique-footprint floor
// (~245 MB). __ldcg gathers (L2-only; measured L1 reuse ~0.8%) gave the
// session's second-best sample (43.68 us); __ldg binary measured
// 43.0-46.0 us over six runs (NAT DVFS, sigma ~1 us). Config space
// (occ 44-88%, MLP 2-8, ordering, LDGSTS, SMEM/shuffle staging,
// full/half-row CTAs) is flat within that band; all traffic-reducing
// restructures rejected with quantified mechanisms (scatter 2x RMW;
// cluster dedup 3% < sync cost; mask dedup trades 21% L2 for >= equal
// SMEM-RMW).
//
// Config: grid 4096 = 2 CTAs per output row (channel halves; L2 window
// ~1.2 batches so DRAM stays at the floor), occ 4 (64-reg budget),
// UF=8 front-batched float4 __ldcg loads, SMEM-staged (idx, weight)
// pairs, streaming stores for the never-re-read output.

#define H 64
#define W 64
#define C 2048
#define CV4 (C / 4)
#define M_MASKS 4
#define P_PTS 512
#define O_POOL 64
#define KCHUNK 8
#define NPAIR 32
#define UF 8

__global__ __launch_bounds__(256, 4)
void point_sample_pool_kernel(const float* __restrict__ feats,
                              const float* __restrict__ pts,
                              float* __restrict__ out)
{
    // blockIdx.x in [0, 4096): bmo*2 + half (b-major ordering preserved)
    const int half = blockIdx.x & 1;
    const int bmo  = blockIdx.x >> 1;
    const int o    = bmo & (O_POOL - 1);
    const int bm   = bmo >> 6;               // b*4 + m
    const int b    = bm >> 2;

    __shared__ int   s_idx[NPAIR];
    __shared__ float s_w[NPAIR];

    const int tid = threadIdx.x;

    if (tid < NPAIR) {
        const int p_local = tid >> 2;
        const int corner  = tid & 3;
        const int p = o * KCHUNK + p_local;
        const float* pp = pts + ((size_t)bm * P_PTS + p) * 2;
        const float iy = pp[0] * (float)(H - 1);
        const float ix = pp[1] * (float)(W - 1);
        const float y0f = floorf(iy);
        const float x0f = floorf(ix);
        const float wy = iy - y0f;
        const float wx = ix - x0f;
        int y0 = (int)y0f; y0 = max(0, min(y0, H - 1));
        int x0 = (int)x0f; x0 = max(0, min(x0, W - 1));
        const int y1 = min(y0 + 1, H - 1);
        const int x1 = min(x0 + 1, W - 1);

        const int   yi  = (corner & 2) ? y1 : y0;
        const int   xi  = (corner & 1) ? x1 : x0;
        const float wyc = (corner & 2) ? wy : (1.0f - wy);
        const float wxc = (corner & 1) ? wx : (1.0f - wx);

        s_idx[tid] = yi * W + xi;
        s_w[tid]   = wyc * wxc * (1.0f / (float)KCHUNK);
    }
    __syncthreads();

    const float4* base = (const float4*)(feats + (size_t)b * (H * W) * C);

    // This CTA owns float4 slots [half*256, half*256+256)
    const int c4 = half * 256 + tid;

    float4 acc0 = make_float4(0.f, 0.f, 0.f, 0.f);
    float4 acc1 = make_float4(0.f, 0.f, 0.f, 0.f);

    #pragma unroll
    for (int j0 = 0; j0 < NPAIR; j0 += UF) {
        float4 v[UF];
        // Front-batch UF independent loads (MLP_p1 = UF), L2-only.
        #pragma unroll
        for (int u = 0; u < UF; u++) {
            v[u] = __ldcg(base + (size_t)s_idx[j0 + u] * CV4 + c4);
        }
        // Then consume
        #pragma unroll
        for (int u = 0; u < UF; u++) {
            const float w = s_w[j0 + u];
            float4& a = (u & 1) ? acc1 : acc0;
            a.x = fmaf(w, v[u].x, a.x);
            a.y = fmaf(w, v[u].y, a.y);
            a.z = fmaf(w, v[u].z, a.z);
            a.w = fmaf(w, v[u].w, a.w);
        }
    }

    acc0.x += acc1.x; acc0.y += acc1.y; acc0.z += acc1.z; acc0.w += acc1.w;

    // Streaming store: output is never re-read.
    float4* op = (float4*)(out + (size_t)bmo * C) + c4;
    __stcs(op, acc0);
}

extern "C" void kernel_launch(void* const* d_in, const int* in_sizes, int n_in,
                              void* d_out, int out_size)
{
    const float* feats = (const float*)d_in[0];
    const float* pts   = (const float*)d_in[1];
    float* out = (float*)d_out;

    const int grid = 8 * M_MASKS * O_POOL * 2;   // 4096 CTAs
    point_sample_pool_kernel<<<grid, 256>>>(feats, pts, out);
}